// round 6
// baseline (speedup 1.0000x reference)
#include <cuda_runtime.h>
#include <cuda_bf16.h>

#define LN 5
#define CN 16
#define HN 256
#define WN 256
#define HW (HN*WN)
#define BN_EPS 1e-5f
#define INV_RATIO 1.25f   /* 1 / (0.4 * 2) */

// One thread = one (i, h, w) output pixel. Fully fused:
// warp -> per-j MLP logit -> online softmax -> weighted nb sum -> final 16x16 conv.
__global__ __launch_bounds__(256) void disco_fused_kernel(
    const float* __restrict__ x,     // [L,C,H,W]
    const float* __restrict__ ptm,   // [1,L,L,4,4]
    const float* __restrict__ w1, const float* __restrict__ b1,
    const float* __restrict__ g1, const float* __restrict__ be1,
    const float* __restrict__ rm1, const float* __restrict__ rv1,
    const float* __restrict__ w2, const float* __restrict__ b2,
    const float* __restrict__ g2, const float* __restrict__ be2,
    const float* __restrict__ rm2, const float* __restrict__ rv2,
    const float* __restrict__ w3, const float* __restrict__ b3,
    const float* __restrict__ g3, const float* __restrict__ be3,
    const float* __restrict__ rm3, const float* __restrict__ rv3,
    const float* __restrict__ w4, const float* __restrict__ b4,
    const float* __restrict__ wm, const float* __restrict__ bm,
    float* __restrict__ out)         // [L,C,H,W]
{
    // ---- shared: folded weights + inverse affines ----
    __shared__ float s_minv[25][6];
    __shared__ float s_w1[16*32];  __shared__ float s_b1[16];
    __shared__ float s_w2[8*16];   __shared__ float s_b2[8];
    __shared__ float s_w3[4*8];    __shared__ float s_b3[4];
    __shared__ float s_w4[4];      __shared__ float s_b4[1];
    __shared__ float s_wm[16*16];  __shared__ float s_bm[16];

    const int tid = threadIdx.x;

    // fold BN scale into conv weights: W' = W * g/sqrt(rv+eps), b' = (b-rm)*scale + be
    for (int idx = tid; idx < 16*32; idx += blockDim.x) {
        int o = idx >> 5;
        s_w1[idx] = w1[idx] * (g1[o] / sqrtf(rv1[o] + BN_EPS));
    }
    for (int idx = tid; idx < 8*16; idx += blockDim.x) {
        int o = idx >> 4;
        s_w2[idx] = w2[idx] * (g2[o] / sqrtf(rv2[o] + BN_EPS));
    }
    for (int idx = tid; idx < 4*8; idx += blockDim.x) {
        int o = idx >> 3;
        s_w3[idx] = w3[idx] * (g3[o] / sqrtf(rv3[o] + BN_EPS));
    }
    for (int idx = tid; idx < 16*16; idx += blockDim.x) s_wm[idx] = wm[idx];
    if (tid < 16) {
        float sc = g1[tid] / sqrtf(rv1[tid] + BN_EPS);
        s_b1[tid] = (b1[tid] - rm1[tid]) * sc + be1[tid];
        s_bm[tid] = bm[tid];
    }
    if (tid < 8) {
        float sc = g2[tid] / sqrtf(rv2[tid] + BN_EPS);
        s_b2[tid] = (b2[tid] - rm2[tid]) * sc + be2[tid];
    }
    if (tid < 4) {
        float sc = g3[tid] / sqrtf(rv3[tid] + BN_EPS);
        s_b3[tid] = (b3[tid] - rm3[tid]) * sc + be3[tid];
        s_w4[tid] = w4[tid];
    }
    if (tid == 0) s_b4[0] = b4[0];

    // analytic inverse of [[a,b,tx],[c,d,ty],[0,0,1]] for all 25 (j,i) pairs
    if (tid < 25) {
        const float* m = ptm + tid * 16;
        float a = m[0], b = m[1], tx = m[3] * INV_RATIO;
        float c = m[4], d = m[5], ty = m[7] * INV_RATIO;
        float inv = 1.0f / (a*d - b*c);
        s_minv[tid][0] =  d * inv;
        s_minv[tid][1] = -b * inv;
        s_minv[tid][2] = (b*ty - d*tx) * inv;
        s_minv[tid][3] = -c * inv;
        s_minv[tid][4] =  a * inv;
        s_minv[tid][5] = (c*tx - a*ty) * inv;
    }
    __syncthreads();

    const int gid = blockIdx.x * blockDim.x + tid;
    if (gid >= LN * HW) return;
    const int i   = gid / HW;
    const int pix = gid - i * HW;
    const int h   = pix >> 8;
    const int w   = pix & 255;
    const float fw = (float)w, fh = (float)h;

    // ego channels x[i][:, h, w]
    float ego[16];
    {
        const float* xi = x + (size_t)i * CN * HW + pix;
        #pragma unroll
        for (int c = 0; c < 16; c++) ego[c] = __ldg(xi + c * HW);
    }

    // hoist j-invariant half of layer 1: egoPart[o] = b1' + W1[o,16:32]·ego
    float egoPart[16];
    #pragma unroll
    for (int o = 0; o < 16; o++) {
        float s = s_b1[o];
        #pragma unroll
        for (int c = 0; c < 16; c++) s += s_w1[o*32 + 16 + c] * ego[c];
        egoPart[o] = s;
    }

    // online softmax state
    float mmax = -3.0e38f;
    float ssum = 0.0f;
    float acc[16];
    #pragma unroll
    for (int c = 0; c < 16; c++) acc[c] = 0.0f;

    #pragma unroll 1
    for (int j = 0; j < LN; j++) {
        // source coords via inv(T[j][i])
        const float* mv = s_minv[j*5 + i];
        float sx = mv[0]*fw + mv[1]*fh + mv[2];
        float sy = mv[3]*fw + mv[4]*fh + mv[5];
        float x0f = floorf(sx), y0f = floorf(sy);
        float wx = sx - x0f,    wy = sy - y0f;
        bool vx0 = (x0f >=  0.0f) && (x0f <= 255.0f);
        bool vx1 = (x0f >= -1.0f) && (x0f <= 254.0f);
        bool vy0 = (y0f >=  0.0f) && (y0f <= 255.0f);
        bool vy1 = (y0f >= -1.0f) && (y0f <= 254.0f);
        float w00 = (vx0 && vy0) ? (1.0f - wx) * (1.0f - wy) : 0.0f;
        float w01 = (vx1 && vy0) ? wx * (1.0f - wy) : 0.0f;
        float w10 = (vx0 && vy1) ? (1.0f - wx) * wy : 0.0f;
        float w11 = (vx1 && vy1) ? wx * wy : 0.0f;
        int ix0 = (int)x0f, iy0 = (int)y0f;
        int cx0 = min(max(ix0,     0), 255);
        int cx1 = min(max(ix0 + 1, 0), 255);
        int cy0 = min(max(iy0,     0), 255);
        int cy1 = min(max(iy0 + 1, 0), 255);
        int o00 = cy0 * WN + cx0, o01 = cy0 * WN + cx1;
        int o10 = cy1 * WN + cx0, o11 = cy1 * WN + cx1;

        // bilinear sample 16 channels of x[j]
        float nb[16];
        const float* xj = x + (size_t)j * CN * HW;
        #pragma unroll
        for (int c = 0; c < 16; c++) {
            const float* bb = xj + c * HW;
            nb[c] = w00 * __ldg(bb + o00) + w01 * __ldg(bb + o01)
                  + w10 * __ldg(bb + o10) + w11 * __ldg(bb + o11);
        }

        // MLP: 32->16->8->4->1 (ego half of layer 1 precomputed)
        float h1[16];
        #pragma unroll
        for (int o = 0; o < 16; o++) {
            float s = egoPart[o];
            #pragma unroll
            for (int c = 0; c < 16; c++) s += s_w1[o*32 + c] * nb[c];
            h1[o] = fmaxf(s, 0.0f);
        }
        float h2[8];
        #pragma unroll
        for (int o = 0; o < 8; o++) {
            float s = s_b2[o];
            #pragma unroll
            for (int c = 0; c < 16; c++) s += s_w2[o*16 + c] * h1[c];
            h2[o] = fmaxf(s, 0.0f);
        }
        float h3[4];
        #pragma unroll
        for (int o = 0; o < 4; o++) {
            float s = s_b3[o];
            #pragma unroll
            for (int c = 0; c < 8; c++) s += s_w3[o*8 + c] * h2[c];
            h3[o] = fmaxf(s, 0.0f);
        }
        float logit = s_b4[0];
        #pragma unroll
        for (int c = 0; c < 4; c++) logit += s_w4[c] * h3[c];
        logit = fmaxf(logit, 0.0f);

        // online softmax update
        float nm    = fmaxf(mmax, logit);
        float scale = __expf(mmax - nm);
        float e     = __expf(logit - nm);
        ssum = ssum * scale + e;
        #pragma unroll
        for (int c = 0; c < 16; c++) acc[c] = acc[c] * scale + e * nb[c];
        mmax = nm;
    }

    // fused = acc/ssum ; out = wm @ fused + bm
    float rinv = 1.0f / ssum;
    float fused[16];
    #pragma unroll
    for (int c = 0; c < 16; c++) fused[c] = acc[c] * rinv;

    float* op = out + (size_t)i * CN * HW + pix;
    #pragma unroll
    for (int o = 0; o < 16; o++) {
        float s = s_bm[o];
        #pragma unroll
        for (int c = 0; c < 16; c++) s += s_wm[o*16 + c] * fused[c];
        op[o * HW] = s;
    }
}

extern "C" void kernel_launch(void* const* d_in, const int* in_sizes, int n_in,
                              void* d_out, int out_size) {
    (void)in_sizes; (void)n_in; (void)out_size;
    // metadata order: x, record_len, pairwise_t_matrix,
    // w1,b1,g1,be1,rm1,rv1, w2,b2,g2,be2,rm2,rv2, w3,b3,g3,be3,rm3,rv3, w4,b4, wm,bm
    const float* x   = (const float*)d_in[0];
    const float* ptm = (const float*)d_in[2];
    const float* w1  = (const float*)d_in[3];
    const float* b1  = (const float*)d_in[4];
    const float* g1  = (const float*)d_in[5];
    const float* be1 = (const float*)d_in[6];
    const float* rm1 = (const float*)d_in[7];
    const float* rv1 = (const float*)d_in[8];
    const float* w2  = (const float*)d_in[9];
    const float* b2  = (const float*)d_in[10];
    const float* g2  = (const float*)d_in[11];
    const float* be2 = (const float*)d_in[12];
    const float* rm2 = (const float*)d_in[13];
    const float* rv2 = (const float*)d_in[14];
    const float* w3  = (const float*)d_in[15];
    const float* b3  = (const float*)d_in[16];
    const float* g3  = (const float*)d_in[17];
    const float* be3 = (const float*)d_in[18];
    const float* rm3 = (const float*)d_in[19];
    const float* rv3 = (const float*)d_in[20];
    const float* w4  = (const float*)d_in[21];
    const float* b4  = (const float*)d_in[22];
    const float* wm  = (const float*)d_in[23];
    const float* bm  = (const float*)d_in[24];
    float* out = (float*)d_out;

    const int total = LN * HW;          // 327680
    const int threads = 256;
    const int blocks = (total + threads - 1) / threads;   // 1280
    disco_fused_kernel<<<blocks, threads>>>(
        x, ptm,
        w1, b1, g1, be1, rm1, rv1,
        w2, b2, g2, be2, rm2, rv2,
        w3, b3, g3, be3, rm3, rv3,
        w4, b4, wm, bm, out);
}

// round 7
// speedup vs baseline: 1.0079x; 1.0079x over previous
#include <cuda_runtime.h>
#include <cuda_bf16.h>

#define LN 5
#define CN 16
#define HN 256
#define WN 256
#define HW (HN*WN)
#define BN_EPS 1e-5f
#define INV_RATIO 1.25f   /* 1 / (0.4 * 2) */

// One thread = one (i, h, w) output pixel. Fully fused:
// warp -> per-j MLP logit -> online softmax -> weighted nb sum -> final 16x16 conv.
__global__ __launch_bounds__(256) void disco_fused_kernel(
    const float* __restrict__ x,     // [L,C,H,W]
    const float* __restrict__ ptm,   // [1,L,L,4,4]
    const float* __restrict__ w1, const float* __restrict__ b1,
    const float* __restrict__ g1, const float* __restrict__ be1,
    const float* __restrict__ rm1, const float* __restrict__ rv1,
    const float* __restrict__ w2, const float* __restrict__ b2,
    const float* __restrict__ g2, const float* __restrict__ be2,
    const float* __restrict__ rm2, const float* __restrict__ rv2,
    const float* __restrict__ w3, const float* __restrict__ b3,
    const float* __restrict__ g3, const float* __restrict__ be3,
    const float* __restrict__ rm3, const float* __restrict__ rv3,
    const float* __restrict__ w4, const float* __restrict__ b4,
    const float* __restrict__ wm, const float* __restrict__ bm,
    float* __restrict__ out)         // [L,C,H,W]
{
    // ---- shared: folded weights + inverse affines ----
    __shared__ float s_minv[25][6];
    __shared__ float s_w1[16*32];  __shared__ float s_b1[16];
    __shared__ float s_w2[8*16];   __shared__ float s_b2[8];
    __shared__ float s_w3[4*8];    __shared__ float s_b3[4];
    __shared__ float s_w4[4];      __shared__ float s_b4[1];
    __shared__ float s_wm[16*16];  __shared__ float s_bm[16];

    const int tid = threadIdx.x;

    // fold BN scale into conv weights: W' = W * g/sqrt(rv+eps), b' = (b-rm)*scale + be
    for (int idx = tid; idx < 16*32; idx += blockDim.x) {
        int o = idx >> 5;
        s_w1[idx] = w1[idx] * (g1[o] / sqrtf(rv1[o] + BN_EPS));
    }
    for (int idx = tid; idx < 8*16; idx += blockDim.x) {
        int o = idx >> 4;
        s_w2[idx] = w2[idx] * (g2[o] / sqrtf(rv2[o] + BN_EPS));
    }
    for (int idx = tid; idx < 4*8; idx += blockDim.x) {
        int o = idx >> 3;
        s_w3[idx] = w3[idx] * (g3[o] / sqrtf(rv3[o] + BN_EPS));
    }
    for (int idx = tid; idx < 16*16; idx += blockDim.x) s_wm[idx] = wm[idx];
    if (tid < 16) {
        float sc = g1[tid] / sqrtf(rv1[tid] + BN_EPS);
        s_b1[tid] = (b1[tid] - rm1[tid]) * sc + be1[tid];
        s_bm[tid] = bm[tid];
    }
    if (tid < 8) {
        float sc = g2[tid] / sqrtf(rv2[tid] + BN_EPS);
        s_b2[tid] = (b2[tid] - rm2[tid]) * sc + be2[tid];
    }
    if (tid < 4) {
        float sc = g3[tid] / sqrtf(rv3[tid] + BN_EPS);
        s_b3[tid] = (b3[tid] - rm3[tid]) * sc + be3[tid];
        s_w4[tid] = w4[tid];
    }
    if (tid == 0) s_b4[0] = b4[0];

    // analytic inverse of [[a,b,tx],[c,d,ty],[0,0,1]] for all 25 (j,i) pairs
    if (tid < 25) {
        const float* m = ptm + tid * 16;
        float a = m[0], b = m[1], tx = m[3] * INV_RATIO;
        float c = m[4], d = m[5], ty = m[7] * INV_RATIO;
        float inv = 1.0f / (a*d - b*c);
        s_minv[tid][0] =  d * inv;
        s_minv[tid][1] = -b * inv;
        s_minv[tid][2] = (b*ty - d*tx) * inv;
        s_minv[tid][3] = -c * inv;
        s_minv[tid][4] =  a * inv;
        s_minv[tid][5] = (c*tx - a*ty) * inv;
    }
    __syncthreads();

    const int gid = blockIdx.x * blockDim.x + tid;
    if (gid >= LN * HW) return;
    const int i   = gid / HW;
    const int pix = gid - i * HW;
    const int h   = pix >> 8;
    const int w   = pix & 255;
    const float fw = (float)w, fh = (float)h;

    // ego channels x[i][:, h, w]
    float ego[16];
    {
        const float* xi = x + (size_t)i * CN * HW + pix;
        #pragma unroll
        for (int c = 0; c < 16; c++) ego[c] = __ldg(xi + c * HW);
    }

    // hoist j-invariant half of layer 1: egoPart[o] = b1' + W1[o,16:32]·ego
    float egoPart[16];
    #pragma unroll
    for (int o = 0; o < 16; o++) {
        float s = s_b1[o];
        #pragma unroll
        for (int c = 0; c < 16; c++) s += s_w1[o*32 + 16 + c] * ego[c];
        egoPart[o] = s;
    }

    // online softmax state
    float mmax = -3.0e38f;
    float ssum = 0.0f;
    float acc[16];
    #pragma unroll
    for (int c = 0; c < 16; c++) acc[c] = 0.0f;

    #pragma unroll 1
    for (int j = 0; j < LN; j++) {
        // source coords via inv(T[j][i])
        const float* mv = s_minv[j*5 + i];
        float sx = mv[0]*fw + mv[1]*fh + mv[2];
        float sy = mv[3]*fw + mv[4]*fh + mv[5];
        float x0f = floorf(sx), y0f = floorf(sy);
        float wx = sx - x0f,    wy = sy - y0f;
        bool vx0 = (x0f >=  0.0f) && (x0f <= 255.0f);
        bool vx1 = (x0f >= -1.0f) && (x0f <= 254.0f);
        bool vy0 = (y0f >=  0.0f) && (y0f <= 255.0f);
        bool vy1 = (y0f >= -1.0f) && (y0f <= 254.0f);
        float w00 = (vx0 && vy0) ? (1.0f - wx) * (1.0f - wy) : 0.0f;
        float w01 = (vx1 && vy0) ? wx * (1.0f - wy) : 0.0f;
        float w10 = (vx0 && vy1) ? (1.0f - wx) * wy : 0.0f;
        float w11 = (vx1 && vy1) ? wx * wy : 0.0f;
        int ix0 = (int)x0f, iy0 = (int)y0f;
        int cx0 = min(max(ix0,     0), 255);
        int cx1 = min(max(ix0 + 1, 0), 255);
        int cy0 = min(max(iy0,     0), 255);
        int cy1 = min(max(iy0 + 1, 0), 255);
        int o00 = cy0 * WN + cx0, o01 = cy0 * WN + cx1;
        int o10 = cy1 * WN + cx0, o11 = cy1 * WN + cx1;

        // bilinear sample 16 channels of x[j]
        float nb[16];
        const float* xj = x + (size_t)j * CN * HW;
        #pragma unroll
        for (int c = 0; c < 16; c++) {
            const float* bb = xj + c * HW;
            nb[c] = w00 * __ldg(bb + o00) + w01 * __ldg(bb + o01)
                  + w10 * __ldg(bb + o10) + w11 * __ldg(bb + o11);
        }

        // MLP: 32->16->8->4->1 (ego half of layer 1 precomputed)
        float h1[16];
        #pragma unroll
        for (int o = 0; o < 16; o++) {
            float s = egoPart[o];
            #pragma unroll
            for (int c = 0; c < 16; c++) s += s_w1[o*32 + c] * nb[c];
            h1[o] = fmaxf(s, 0.0f);
        }
        float h2[8];
        #pragma unroll
        for (int o = 0; o < 8; o++) {
            float s = s_b2[o];
            #pragma unroll
            for (int c = 0; c < 16; c++) s += s_w2[o*16 + c] * h1[c];
            h2[o] = fmaxf(s, 0.0f);
        }
        float h3[4];
        #pragma unroll
        for (int o = 0; o < 4; o++) {
            float s = s_b3[o];
            #pragma unroll
            for (int c = 0; c < 8; c++) s += s_w3[o*8 + c] * h2[c];
            h3[o] = fmaxf(s, 0.0f);
        }
        float logit = s_b4[0];
        #pragma unroll
        for (int c = 0; c < 4; c++) logit += s_w4[c] * h3[c];
        logit = fmaxf(logit, 0.0f);

        // online softmax update
        float nm    = fmaxf(mmax, logit);
        float scale = __expf(mmax - nm);
        float e     = __expf(logit - nm);
        ssum = ssum * scale + e;
        #pragma unroll
        for (int c = 0; c < 16; c++) acc[c] = acc[c] * scale + e * nb[c];
        mmax = nm;
    }

    // fused = acc/ssum ; out = wm @ fused + bm
    float rinv = 1.0f / ssum;
    float fused[16];
    #pragma unroll
    for (int c = 0; c < 16; c++) fused[c] = acc[c] * rinv;

    float* op = out + (size_t)i * CN * HW + pix;
    #pragma unroll
    for (int o = 0; o < 16; o++) {
        float s = s_bm[o];
        #pragma unroll
        for (int c = 0; c < 16; c++) s += s_wm[o*16 + c] * fused[c];
        op[o * HW] = s;
    }
}

extern "C" void kernel_launch(void* const* d_in, const int* in_sizes, int n_in,
                              void* d_out, int out_size) {
    (void)in_sizes; (void)n_in; (void)out_size;
    // metadata order: x, record_len, pairwise_t_matrix,
    // w1,b1,g1,be1,rm1,rv1, w2,b2,g2,be2,rm2,rv2, w3,b3,g3,be3,rm3,rv3, w4,b4, wm,bm
    const float* x   = (const float*)d_in[0];
    const float* ptm = (const float*)d_in[2];
    const float* w1  = (const float*)d_in[3];
    const float* b1  = (const float*)d_in[4];
    const float* g1  = (const float*)d_in[5];
    const float* be1 = (const float*)d_in[6];
    const float* rm1 = (const float*)d_in[7];
    const float* rv1 = (const float*)d_in[8];
    const float* w2  = (const float*)d_in[9];
    const float* b2  = (const float*)d_in[10];
    const float* g2  = (const float*)d_in[11];
    const float* be2 = (const float*)d_in[12];
    const float* rm2 = (const float*)d_in[13];
    const float* rv2 = (const float*)d_in[14];
    const float* w3  = (const float*)d_in[15];
    const float* b3  = (const float*)d_in[16];
    const float* g3  = (const float*)d_in[17];
    const float* be3 = (const float*)d_in[18];
    const float* rm3 = (const float*)d_in[19];
    const float* rv3 = (const float*)d_in[20];
    const float* w4  = (const float*)d_in[21];
    const float* b4  = (const float*)d_in[22];
    const float* wm  = (const float*)d_in[23];
    const float* bm  = (const float*)d_in[24];
    float* out = (float*)d_out;

    const int total = LN * HW;          // 327680
    const int threads = 256;
    const int blocks = (total + threads - 1) / threads;   // 1280
    disco_fused_kernel<<<blocks, threads>>>(
        x, ptm,
        w1, b1, g1, be1, rm1, rv1,
        w2, b2, g2, be2, rm2, rv2,
        w3, b3, g3, be3, rm3, rv3,
        w4, b4, wm, bm, out);
}

// round 8
// speedup vs baseline: 1.0822x; 1.0737x over previous
#include <cuda_runtime.h>
#include <cuda_bf16.h>

#define LN 5
#define CN 16
#define HN 256
#define WN 256
#define HW (HN*WN)
#define BN_EPS 1e-5f
#define INV_RATIO 1.25f   /* 1 / (0.4 * 2) */

// All loop-invariant parameters live in the constant bank -> LDCU/uniform port,
// keeping the l1tex pipe free for the bilinear gathers.
struct Consts {
    float minv[25][6];     // inverse affines, scaled translations
    float w1n[16][16];     // layer1, nb half (BN-folded)
    float w1e[16][16];     // layer1, ego half (BN-folded)
    float b1[16];
    float w2[8][16];  float b2[8];
    float w3[4][8];   float b3[4];
    float w4[4];      float b4;
    float wm[16][16]; float bm[16];
};

__constant__ Consts cc;      // read by the main kernel
__device__   Consts g_fold;  // staging: written by fold kernel, memcpy'd to cc

// ---- prologue: BN-fold + affine inversion into the staging struct ----
__global__ __launch_bounds__(256) void fold_kernel(
    const float* __restrict__ ptm,
    const float* __restrict__ w1, const float* __restrict__ b1,
    const float* __restrict__ g1, const float* __restrict__ be1,
    const float* __restrict__ rm1, const float* __restrict__ rv1,
    const float* __restrict__ w2, const float* __restrict__ b2,
    const float* __restrict__ g2, const float* __restrict__ be2,
    const float* __restrict__ rm2, const float* __restrict__ rv2,
    const float* __restrict__ w3, const float* __restrict__ b3,
    const float* __restrict__ g3, const float* __restrict__ be3,
    const float* __restrict__ rm3, const float* __restrict__ rv3,
    const float* __restrict__ w4, const float* __restrict__ b4,
    const float* __restrict__ wm, const float* __restrict__ bm)
{
    const int tid = threadIdx.x;

    // layer 1: split into nb half (cols 0..15) and ego half (cols 16..31)
    for (int idx = tid; idx < 16*32; idx += blockDim.x) {
        int o = idx >> 5, c = idx & 31;
        float v = w1[idx] * (g1[o] * rsqrtf(rv1[o] + BN_EPS));
        if (c < 16) g_fold.w1n[o][c]      = v;
        else        g_fold.w1e[o][c - 16] = v;
    }
    for (int idx = tid; idx < 8*16; idx += blockDim.x) {
        int o = idx >> 4;
        g_fold.w2[o][idx & 15] = w2[idx] * (g2[o] * rsqrtf(rv2[o] + BN_EPS));
    }
    for (int idx = tid; idx < 4*8; idx += blockDim.x) {
        int o = idx >> 3;
        g_fold.w3[o][idx & 7] = w3[idx] * (g3[o] * rsqrtf(rv3[o] + BN_EPS));
    }
    for (int idx = tid; idx < 16*16; idx += blockDim.x)
        g_fold.wm[idx >> 4][idx & 15] = wm[idx];

    if (tid < 16) {
        float sc = g1[tid] * rsqrtf(rv1[tid] + BN_EPS);
        g_fold.b1[tid] = (b1[tid] - rm1[tid]) * sc + be1[tid];
        g_fold.bm[tid] = bm[tid];
    }
    if (tid < 8) {
        float sc = g2[tid] * rsqrtf(rv2[tid] + BN_EPS);
        g_fold.b2[tid] = (b2[tid] - rm2[tid]) * sc + be2[tid];
    }
    if (tid < 4) {
        float sc = g3[tid] * rsqrtf(rv3[tid] + BN_EPS);
        g_fold.b3[tid] = (b3[tid] - rm3[tid]) * sc + be3[tid];
        g_fold.w4[tid] = w4[tid];
    }
    if (tid == 0) g_fold.b4 = b4[0];

    // analytic inverse of [[a,b,tx],[c,d,ty],[0,0,1]] for all 25 (j,i) pairs
    if (tid < 25) {
        const float* m = ptm + tid * 16;
        float a = m[0], b = m[1], tx = m[3] * INV_RATIO;
        float c = m[4], d = m[5], ty = m[7] * INV_RATIO;
        float inv = 1.0f / (a*d - b*c);
        g_fold.minv[tid][0] =  d * inv;
        g_fold.minv[tid][1] = -b * inv;
        g_fold.minv[tid][2] = (b*ty - d*tx) * inv;
        g_fold.minv[tid][3] = -c * inv;
        g_fold.minv[tid][4] =  a * inv;
        g_fold.minv[tid][5] = (c*tx - a*ty) * inv;
    }
}

// ---- main fused kernel: one thread = one (i, h, w) output pixel ----
__global__ __launch_bounds__(256, 2) void disco_fused_kernel(
    const float* __restrict__ x,     // [L,C,H,W]
    float* __restrict__ out)         // [L,C,H,W]
{
    const int gid = blockIdx.x * blockDim.x + threadIdx.x;
    const int i   = gid / HW;
    const int pix = gid - i * HW;
    const int h   = pix >> 8;
    const int w   = pix & 255;
    const float fw = (float)w, fh = (float)h;

    // ego channels x[i][:, h, w]
    float ego[16];
    {
        const float* xi = x + (size_t)i * CN * HW + pix;
        #pragma unroll
        for (int c = 0; c < 16; c++) ego[c] = __ldg(xi + c * HW);
    }

    // hoist j-invariant half of layer 1: egoPart[o] = b1' + W1e[o]·ego
    float egoPart[16];
    #pragma unroll
    for (int o = 0; o < 16; o++) {
        float s = cc.b1[o];
        #pragma unroll
        for (int c = 0; c < 16; c++) s += cc.w1e[o][c] * ego[c];
        egoPart[o] = s;
    }

    // online softmax state
    float mmax = -3.0e38f;
    float ssum = 0.0f;
    float acc[16];
    #pragma unroll
    for (int c = 0; c < 16; c++) acc[c] = 0.0f;

    #pragma unroll 1
    for (int j = 0; j < LN; j++) {
        // source coords via inv(T[j][i])
        const int mi = j * 5 + i;
        float sx = cc.minv[mi][0]*fw + cc.minv[mi][1]*fh + cc.minv[mi][2];
        float sy = cc.minv[mi][3]*fw + cc.minv[mi][4]*fh + cc.minv[mi][5];
        float x0f = floorf(sx), y0f = floorf(sy);
        float wx = sx - x0f,    wy = sy - y0f;
        bool vx0 = (x0f >=  0.0f) && (x0f <= 255.0f);
        bool vx1 = (x0f >= -1.0f) && (x0f <= 254.0f);
        bool vy0 = (y0f >=  0.0f) && (y0f <= 255.0f);
        bool vy1 = (y0f >= -1.0f) && (y0f <= 254.0f);
        float w00 = (vx0 && vy0) ? (1.0f - wx) * (1.0f - wy) : 0.0f;
        float w01 = (vx1 && vy0) ? wx * (1.0f - wy) : 0.0f;
        float w10 = (vx0 && vy1) ? (1.0f - wx) * wy : 0.0f;
        float w11 = (vx1 && vy1) ? wx * wy : 0.0f;
        int ix0 = (int)x0f, iy0 = (int)y0f;
        int cx0 = min(max(ix0,     0), 255);
        int cx1 = min(max(ix0 + 1, 0), 255);
        int cy0 = min(max(iy0,     0), 255);
        int cy1 = min(max(iy0 + 1, 0), 255);
        int o00 = cy0 * WN + cx0, o01 = cy0 * WN + cx1;
        int o10 = cy1 * WN + cx0, o11 = cy1 * WN + cx1;

        // bilinear sample 16 channels of x[j]
        float nb[16];
        const float* xj = x + (size_t)j * CN * HW;
        #pragma unroll
        for (int c = 0; c < 16; c++) {
            const float* bb = xj + c * HW;
            nb[c] = w00 * __ldg(bb + o00) + w01 * __ldg(bb + o01)
                  + w10 * __ldg(bb + o10) + w11 * __ldg(bb + o11);
        }

        // MLP: 32->16->8->4->1 (ego half of layer 1 precomputed)
        float h1[16];
        #pragma unroll
        for (int o = 0; o < 16; o++) {
            float s = egoPart[o];
            #pragma unroll
            for (int c = 0; c < 16; c++) s += cc.w1n[o][c] * nb[c];
            h1[o] = fmaxf(s, 0.0f);
        }
        float h2[8];
        #pragma unroll
        for (int o = 0; o < 8; o++) {
            float s = cc.b2[o];
            #pragma unroll
            for (int c = 0; c < 16; c++) s += cc.w2[o][c] * h1[c];
            h2[o] = fmaxf(s, 0.0f);
        }
        float h3[4];
        #pragma unroll
        for (int o = 0; o < 4; o++) {
            float s = cc.b3[o];
            #pragma unroll
            for (int c = 0; c < 8; c++) s += cc.w3[o][c] * h2[c];
            h3[o] = fmaxf(s, 0.0f);
        }
        float logit = cc.b4;
        #pragma unroll
        for (int c = 0; c < 4; c++) logit += cc.w4[c] * h3[c];
        logit = fmaxf(logit, 0.0f);

        // online softmax update
        float nm    = fmaxf(mmax, logit);
        float scale = __expf(mmax - nm);
        float e     = __expf(logit - nm);
        ssum = ssum * scale + e;
        #pragma unroll
        for (int c = 0; c < 16; c++) acc[c] = acc[c] * scale + e * nb[c];
        mmax = nm;
    }

    // out = wm @ (acc/ssum) + bm  ->  (wm @ acc) * rinv + bm
    float rinv = 1.0f / ssum;
    float* op = out + (size_t)i * CN * HW + pix;
    #pragma unroll
    for (int o = 0; o < 16; o++) {
        float s = 0.0f;
        #pragma unroll
        for (int c = 0; c < 16; c++) s += cc.wm[o][c] * acc[c];
        op[o * HW] = s * rinv + cc.bm[o];
    }
}

extern "C" void kernel_launch(void* const* d_in, const int* in_sizes, int n_in,
                              void* d_out, int out_size) {
    (void)in_sizes; (void)n_in; (void)out_size;
    // metadata order: x, record_len, pairwise_t_matrix,
    // w1,b1,g1,be1,rm1,rv1, w2,b2,g2,be2,rm2,rv2, w3,b3,g3,be3,rm3,rv3, w4,b4, wm,bm
    const float* x   = (const float*)d_in[0];
    const float* ptm = (const float*)d_in[2];

    fold_kernel<<<1, 256>>>(
        ptm,
        (const float*)d_in[3],  (const float*)d_in[4],
        (const float*)d_in[5],  (const float*)d_in[6],
        (const float*)d_in[7],  (const float*)d_in[8],
        (const float*)d_in[9],  (const float*)d_in[10],
        (const float*)d_in[11], (const float*)d_in[12],
        (const float*)d_in[13], (const float*)d_in[14],
        (const float*)d_in[15], (const float*)d_in[16],
        (const float*)d_in[17], (const float*)d_in[18],
        (const float*)d_in[19], (const float*)d_in[20],
        (const float*)d_in[21], (const float*)d_in[22],
        (const float*)d_in[23], (const float*)d_in[24]);

    // stage -> constant bank (graph-capturable D2D memcpy node)
    void* foldAddr = nullptr;
    cudaGetSymbolAddress(&foldAddr, g_fold);
    cudaMemcpyToSymbolAsync(cc, foldAddr, sizeof(Consts), 0,
                            cudaMemcpyDeviceToDevice, 0);

    const int total = LN * HW;          // 327680
    const int threads = 256;
    const int blocks = (total + threads - 1) / threads;   // 1280
    disco_fused_kernel<<<blocks, threads>>>(x, (float*)d_out);
}

// round 9
// speedup vs baseline: 1.3674x; 1.2635x over previous
#include <cuda_runtime.h>
#include <cuda_bf16.h>

#define LN 5
#define CN 16
#define HN 256
#define WN 256
#define HW (HN*WN)
#define BN_EPS 1e-5f
#define INV_RATIO 1.25f   /* 1 / (0.4 * 2) */

// All loop-invariant parameters live in the constant bank -> LDCU/uniform port,
// keeping the l1tex pipe free for the bilinear gathers.
struct Consts {
    float minv[25][6];     // inverse affines, scaled translations
    float w1n[16][16];     // layer1, nb half (BN-folded)
    float w1e[16][16];     // layer1, ego half (BN-folded)
    float b1[16];
    float w2[8][16];  float b2[8];
    float w3[4][8];   float b3[4];
    float w4[4];      float b4;
    float wm[16][16]; float bm[16];
};

__constant__ Consts cc;      // read by the main kernel
__device__   Consts g_fold;  // staging: written by fold kernel, memcpy'd to cc

// ---- prologue: BN-fold + affine inversion into the staging struct ----
__global__ __launch_bounds__(256) void fold_kernel(
    const float* __restrict__ ptm,
    const float* __restrict__ w1, const float* __restrict__ b1,
    const float* __restrict__ g1, const float* __restrict__ be1,
    const float* __restrict__ rm1, const float* __restrict__ rv1,
    const float* __restrict__ w2, const float* __restrict__ b2,
    const float* __restrict__ g2, const float* __restrict__ be2,
    const float* __restrict__ rm2, const float* __restrict__ rv2,
    const float* __restrict__ w3, const float* __restrict__ b3,
    const float* __restrict__ g3, const float* __restrict__ be3,
    const float* __restrict__ rm3, const float* __restrict__ rv3,
    const float* __restrict__ w4, const float* __restrict__ b4,
    const float* __restrict__ wm, const float* __restrict__ bm)
{
    const int tid = threadIdx.x;

    // layer 1: split into nb half (cols 0..15) and ego half (cols 16..31)
    for (int idx = tid; idx < 16*32; idx += blockDim.x) {
        int o = idx >> 5, c = idx & 31;
        float v = w1[idx] * (g1[o] * rsqrtf(rv1[o] + BN_EPS));
        if (c < 16) g_fold.w1n[o][c]      = v;
        else        g_fold.w1e[o][c - 16] = v;
    }
    for (int idx = tid; idx < 8*16; idx += blockDim.x) {
        int o = idx >> 4;
        g_fold.w2[o][idx & 15] = w2[idx] * (g2[o] * rsqrtf(rv2[o] + BN_EPS));
    }
    for (int idx = tid; idx < 4*8; idx += blockDim.x) {
        int o = idx >> 3;
        g_fold.w3[o][idx & 7] = w3[idx] * (g3[o] * rsqrtf(rv3[o] + BN_EPS));
    }
    for (int idx = tid; idx < 16*16; idx += blockDim.x)
        g_fold.wm[idx >> 4][idx & 15] = wm[idx];

    if (tid < 16) {
        float sc = g1[tid] * rsqrtf(rv1[tid] + BN_EPS);
        g_fold.b1[tid] = (b1[tid] - rm1[tid]) * sc + be1[tid];
        g_fold.bm[tid] = bm[tid];
    }
    if (tid < 8) {
        float sc = g2[tid] * rsqrtf(rv2[tid] + BN_EPS);
        g_fold.b2[tid] = (b2[tid] - rm2[tid]) * sc + be2[tid];
    }
    if (tid < 4) {
        float sc = g3[tid] * rsqrtf(rv3[tid] + BN_EPS);
        g_fold.b3[tid] = (b3[tid] - rm3[tid]) * sc + be3[tid];
        g_fold.w4[tid] = w4[tid];
    }
    if (tid == 0) g_fold.b4 = b4[0];

    // analytic inverse of [[a,b,tx],[c,d,ty],[0,0,1]] for all 25 (j,i) pairs
    if (tid < 25) {
        const float* m = ptm + tid * 16;
        float a = m[0], b = m[1], tx = m[3] * INV_RATIO;
        float c = m[4], d = m[5], ty = m[7] * INV_RATIO;
        float inv = 1.0f / (a*d - b*c);
        g_fold.minv[tid][0] =  d * inv;
        g_fold.minv[tid][1] = -b * inv;
        g_fold.minv[tid][2] = (b*ty - d*tx) * inv;
        g_fold.minv[tid][3] = -c * inv;
        g_fold.minv[tid][4] =  a * inv;
        g_fold.minv[tid][5] = (c*tx - a*ty) * inv;
    }
}

// ---- main fused kernel: one thread = one (i, h, w) output pixel ----
// min 3 CTAs/SM (<=84 regs) to get enough warps to hide the gather latency.
__global__ __launch_bounds__(256, 3) void disco_fused_kernel(
    const float* __restrict__ x,     // [L,C,H,W]
    float* __restrict__ out)         // [L,C,H,W]
{
    const int gid = blockIdx.x * blockDim.x + threadIdx.x;
    const int i   = gid / HW;
    const int pix = gid - i * HW;
    const int h   = pix >> 8;
    const int w   = pix & 255;
    const float fw = (float)w, fh = (float)h;

    // ego channels x[i][:, h, w] -> j-invariant half of layer 1:
    // egoPart[o] = b1' + W1e[o]·ego   (ego regs die here)
    float egoPart[16];
    {
        float ego[16];
        const float* xi = x + (size_t)i * CN * HW + pix;
        #pragma unroll
        for (int c = 0; c < 16; c++) ego[c] = __ldg(xi + c * HW);
        #pragma unroll
        for (int o = 0; o < 16; o++) {
            float s = cc.b1[o];
            #pragma unroll
            for (int c = 0; c < 16; c++) s += cc.w1e[o][c] * ego[c];
            egoPart[o] = s;
        }
    }

    // softmax without max-tracking: logits are ReLU'd (>=0) and small for this
    // network, so exp() cannot overflow; e >= 1 so ssum >= L.
    float ssum = 0.0f;
    float acc[16];
    #pragma unroll
    for (int c = 0; c < 16; c++) acc[c] = 0.0f;

    #pragma unroll 1
    for (int j = 0; j < LN; j++) {
        // source coords via inv(T[j][i])
        const int mi = j * 5 + i;
        float sx = cc.minv[mi][0]*fw + cc.minv[mi][1]*fh + cc.minv[mi][2];
        float sy = cc.minv[mi][3]*fw + cc.minv[mi][4]*fh + cc.minv[mi][5];
        float x0f = floorf(sx), y0f = floorf(sy);
        float wx = sx - x0f,    wy = sy - y0f;
        bool vx0 = (x0f >=  0.0f) && (x0f <= 255.0f);
        bool vx1 = (x0f >= -1.0f) && (x0f <= 254.0f);
        bool vy0 = (y0f >=  0.0f) && (y0f <= 255.0f);
        bool vy1 = (y0f >= -1.0f) && (y0f <= 254.0f);
        float w00 = (vx0 && vy0) ? (1.0f - wx) * (1.0f - wy) : 0.0f;
        float w01 = (vx1 && vy0) ? wx * (1.0f - wy) : 0.0f;
        float w10 = (vx0 && vy1) ? (1.0f - wx) * wy : 0.0f;
        float w11 = (vx1 && vy1) ? wx * wy : 0.0f;
        int ix0 = (int)x0f, iy0 = (int)y0f;
        int cx0 = min(max(ix0,     0), 255);
        int cx1 = min(max(ix0 + 1, 0), 255);
        int cy0 = min(max(iy0,     0), 255);
        int cy1 = min(max(iy0 + 1, 0), 255);
        int o00 = cy0 * WN + cx0, o01 = cy0 * WN + cx1;
        int o10 = cy1 * WN + cx0, o11 = cy1 * WN + cx1;

        // bilinear sample 16 channels of x[j]
        float nb[16];
        const float* xj = x + (size_t)j * CN * HW;
        #pragma unroll
        for (int c = 0; c < 16; c++) {
            const float* bb = xj + c * HW;
            nb[c] = w00 * __ldg(bb + o00) + w01 * __ldg(bb + o01)
                  + w10 * __ldg(bb + o10) + w11 * __ldg(bb + o11);
        }

        // MLP: 32->16->8->4->1 (ego half of layer 1 precomputed)
        float h1[16];
        #pragma unroll
        for (int o = 0; o < 16; o++) {
            float s = egoPart[o];
            #pragma unroll
            for (int c = 0; c < 16; c++) s += cc.w1n[o][c] * nb[c];
            h1[o] = fmaxf(s, 0.0f);
        }
        float h2[8];
        #pragma unroll
        for (int o = 0; o < 8; o++) {
            float s = cc.b2[o];
            #pragma unroll
            for (int c = 0; c < 16; c++) s += cc.w2[o][c] * h1[c];
            h2[o] = fmaxf(s, 0.0f);
        }
        float h3[4];
        #pragma unroll
        for (int o = 0; o < 4; o++) {
            float s = cc.b3[o];
            #pragma unroll
            for (int c = 0; c < 8; c++) s += cc.w3[o][c] * h2[c];
            h3[o] = fmaxf(s, 0.0f);
        }
        float logit = cc.b4;
        #pragma unroll
        for (int c = 0; c < 4; c++) logit += cc.w4[c] * h3[c];
        logit = fmaxf(logit, 0.0f);

        // un-normalized softmax accumulate (no rescale chain)
        float e = __expf(logit);
        ssum += e;
        #pragma unroll
        for (int c = 0; c < 16; c++) acc[c] += e * nb[c];
    }

    // out = wm @ (acc/ssum) + bm  ->  (wm @ acc) * rinv + bm
    float rinv = 1.0f / ssum;
    float* op = out + (size_t)i * CN * HW + pix;
    #pragma unroll
    for (int o = 0; o < 16; o++) {
        float s = 0.0f;
        #pragma unroll
        for (int c = 0; c < 16; c++) s += cc.wm[o][c] * acc[c];
        op[o * HW] = s * rinv + cc.bm[o];
    }
}

extern "C" void kernel_launch(void* const* d_in, const int* in_sizes, int n_in,
                              void* d_out, int out_size) {
    (void)in_sizes; (void)n_in; (void)out_size;
    // metadata order: x, record_len, pairwise_t_matrix,
    // w1,b1,g1,be1,rm1,rv1, w2,b2,g2,be2,rm2,rv2, w3,b3,g3,be3,rm3,rv3, w4,b4, wm,bm
    const float* x   = (const float*)d_in[0];
    const float* ptm = (const float*)d_in[2];

    fold_kernel<<<1, 256>>>(
        ptm,
        (const float*)d_in[3],  (const float*)d_in[4],
        (const float*)d_in[5],  (const float*)d_in[6],
        (const float*)d_in[7],  (const float*)d_in[8],
        (const float*)d_in[9],  (const float*)d_in[10],
        (const float*)d_in[11], (const float*)d_in[12],
        (const float*)d_in[13], (const float*)d_in[14],
        (const float*)d_in[15], (const float*)d_in[16],
        (const float*)d_in[17], (const float*)d_in[18],
        (const float*)d_in[19], (const float*)d_in[20],
        (const float*)d_in[21], (const float*)d_in[22],
        (const float*)d_in[23], (const float*)d_in[24]);

    // stage -> constant bank (graph-capturable D2D memcpy node)
    void* foldAddr = nullptr;
    cudaGetSymbolAddress(&foldAddr, g_fold);
    cudaMemcpyToSymbolAsync(cc, foldAddr, sizeof(Consts), 0,
                            cudaMemcpyDeviceToDevice, 0);

    const int total = LN * HW;          // 327680
    const int threads = 256;
    const int blocks = (total + threads - 1) / threads;   // 1280
    disco_fused_kernel<<<blocks, threads>>>(x, (float*)d_out);
}